// round 10
// baseline (speedup 1.0000x reference)
#include <cuda_runtime.h>

// Flow-warp bilinear, direct gather, y-paired pixels. Row taps (x0, x0+1)
// fetched with ONE aligned LDG.64 at (x0 & ~1) + a 50%-predicated scalar for
// odd x0. 8B loads never cross 128B lines and carry no wavefront width
// penalty, halving the full-rate gather instruction count vs scalar taps.
// out[b,c,y,x] = bilerp(src[b,c], clamp(y+flow[b,0,y,x]), clamp(x+flow[b,1,y,x]))
// B=8, C=16, H=W=512.
// Edge trick: clamp x0,y0 <= 510; when floor==511 the fractional weight is
// exactly 1.0, so results are identical and all taps stay in bounds.

#define B_ 8
#define C_ 16
#define H_ 512
#define W_ 512
#define HW_ (H_ * W_)
#define CHW_ (C_ * HW_)

__global__ void __launch_bounds__(256) warp_gather_p64_kernel(
    const float* __restrict__ src,
    const float* __restrict__ flow,
    float* __restrict__ out)
{
    int idx = blockIdx.x * blockDim.x + threadIdx.x;   // over B * H/2 * W
    int x   = idx & (W_ - 1);
    int ry  = (idx >> 9) & 255;
    int b   = idx >> 17;
    int y   = ry * 2;

    const float* __restrict__ fby = flow + b * 2 * HW_;
    const float* __restrict__ fbx = fby + HW_;

    int   gE[2];          // y0*512 + (x0 & ~1)
    bool  oddv[2];
    float wxv[2], wyv[2];

#pragma unroll
    for (int k = 0; k < 2; ++k) {
        int yy = y + k;
        int fo = yy * W_ + x;
        float fy = __ldg(fby + fo);
        float fx = __ldg(fbx + fo);
        // reference's normalize->unnormalize cancels exactly
        float py = fminf(fmaxf((float)yy + fy, 0.0f), (float)(H_ - 1));
        float px = fminf(fmaxf((float)x  + fx, 0.0f), (float)(W_ - 1));
        float y0f = floorf(py);
        float x0f = floorf(px);
        int y0 = min((int)y0f, H_ - 2);
        int x0 = min((int)x0f, W_ - 2);
        wyv[k] = py - (float)y0;
        wxv[k] = px - (float)x0;
        oddv[k] = (x0 & 1);
        gE[k] = (y0 << 9) + (x0 & ~1);
    }

    const float* __restrict__ sb = src + b * CHW_;
    float* __restrict__ ob = out + b * CHW_ + y * W_ + x;

    const int  gA = gE[0],  gB = gE[1];
    const bool oA = oddv[0], oB = oddv[1];

#pragma unroll
    for (int c = 0; c < C_; ++c) {
        const float* __restrict__ sc = sb + c * HW_;

        // pixel A rows
        float2 A0 = *(const float2*)(sc + gA);         // (e, e+1) of row y0
        float2 A1 = *(const float2*)(sc + gA + W_);    // row y0+1
        float xA0 = oA ? __ldg(sc + gA + 2)      : 0.0f;   // @p LDG, 50% lanes
        float xA1 = oA ? __ldg(sc + gA + W_ + 2) : 0.0f;

        // pixel B rows
        float2 B0 = *(const float2*)(sc + gB);
        float2 B1 = *(const float2*)(sc + gB + W_);
        float xB0 = oB ? __ldg(sc + gB + 2)      : 0.0f;
        float xB1 = oB ? __ldg(sc + gB + W_ + 2) : 0.0f;

        float a00 = oA ? A0.y : A0.x;
        float a01 = oA ? xA0  : A0.y;
        float a10 = oA ? A1.y : A1.x;
        float a11 = oA ? xA1  : A1.y;

        float b00 = oB ? B0.y : B0.x;
        float b01 = oB ? xB0  : B0.y;
        float b10 = oB ? B1.y : B1.x;
        float b11 = oB ? xB1  : B1.y;

        float atop = fmaf(wxv[0], a01 - a00, a00);
        float abot = fmaf(wxv[0], a11 - a10, a10);
        float btop = fmaf(wxv[1], b01 - b00, b00);
        float bbot = fmaf(wxv[1], b11 - b10, b10);

        float* __restrict__ oc = ob + c * HW_;
        oc[0]  = fmaf(wyv[0], abot - atop, atop);
        oc[W_] = fmaf(wyv[1], bbot - btop, btop);
    }
}

extern "C" void kernel_launch(void* const* d_in, const int* in_sizes, int n_in,
                              void* d_out, int out_size)
{
    const float* src  = (const float*)d_in[0];
    const float* flow = (const float*)d_in[1];
    float* out        = (float*)d_out;

    const int total = B_ * (H_ / 2) * W_;   // 1,048,576 threads
    warp_gather_p64_kernel<<<total / 256, 256>>>(src, flow, out);
}

// round 11
// speedup vs baseline: 1.2073x; 1.2073x over previous
#include <cuda_runtime.h>

// Flow-warp bilinear, direct scalar gather, 2 y-adjacent pixels per thread.
// R5 geometry (proven optimal across 6 structural variants) + streaming
// cache hints on write-once outputs / read-once flow so src owns L1/L2.
// out[b,c,y,x] = bilerp(src[b,c], clamp(y+flow[b,0,y,x]), clamp(x+flow[b,1,y,x]))
// B=8, C=16, H=W=512.
// Edge trick: clamp x0,y0 <= 510; when floor==511 the fractional weight is
// exactly 1.0 so the result is identical and the +1 taps stay in bounds.

#define B_ 8
#define C_ 16
#define H_ 512
#define W_ 512
#define HW_ (H_ * W_)
#define CHW_ (C_ * HW_)

__global__ void __launch_bounds__(256) warp_gather2s_kernel(
    const float* __restrict__ src,
    const float* __restrict__ flow,
    float* __restrict__ out)
{
    int idx = blockIdx.x * blockDim.x + threadIdx.x;   // over B * H/2 * W
    int x   = idx & (W_ - 1);
    int ry  = (idx >> 9) & 255;
    int b   = idx >> 17;
    int y   = ry * 2;

    const float* __restrict__ fby = flow + b * 2 * HW_;
    const float* __restrict__ fbx = fby + HW_;

    int   g00[2];
    float wxv[2], wyv[2];

#pragma unroll
    for (int k = 0; k < 2; ++k) {
        int yy = y + k;
        int fo = yy * W_ + x;
        float fy = __ldcs(fby + fo);            // read-once: stream
        float fx = __ldcs(fbx + fo);
        // reference's normalize->unnormalize cancels exactly
        float py = fminf(fmaxf((float)yy + fy, 0.0f), (float)(H_ - 1));
        float px = fminf(fmaxf((float)x  + fx, 0.0f), (float)(W_ - 1));
        float y0f = floorf(py);
        float x0f = floorf(px);
        int y0 = min((int)y0f, H_ - 2);         // edge: weight becomes exactly 1
        int x0 = min((int)x0f, W_ - 2);
        wyv[k] = py - (float)y0;
        wxv[k] = px - (float)x0;
        g00[k] = (y0 << 9) + x0;
    }

    const float* __restrict__ sb = src + b * CHW_;
    float* __restrict__ ob = out + b * CHW_ + y * W_ + x;

    const int gA = g00[0];
    const int gB = g00[1];

#pragma unroll
    for (int c = 0; c < C_; ++c) {
        const float* __restrict__ sc = sb + c * HW_;
        float a00 = __ldg(sc + gA);
        float a01 = __ldg(sc + gA + 1);
        float a10 = __ldg(sc + gA + W_);
        float a11 = __ldg(sc + gA + W_ + 1);
        float b00 = __ldg(sc + gB);
        float b01 = __ldg(sc + gB + 1);
        float b10 = __ldg(sc + gB + W_);
        float b11 = __ldg(sc + gB + W_ + 1);

        float atop = fmaf(wxv[0], a01 - a00, a00);
        float abot = fmaf(wxv[0], a11 - a10, a10);
        float btop = fmaf(wxv[1], b01 - b00, b00);
        float bbot = fmaf(wxv[1], b11 - b10, b10);

        float* __restrict__ oc = ob + c * HW_;
        __stcs(oc,      fmaf(wyv[0], abot - atop, atop));   // write-once: stream
        __stcs(oc + W_, fmaf(wyv[1], bbot - btop, btop));
    }
}

extern "C" void kernel_launch(void* const* d_in, const int* in_sizes, int n_in,
                              void* d_out, int out_size)
{
    const float* src  = (const float*)d_in[0];
    const float* flow = (const float*)d_in[1];
    float* out        = (float*)d_out;

    const int total = B_ * (H_ / 2) * W_;   // 1,048,576 threads
    warp_gather2s_kernel<<<total / 256, 256>>>(src, flow, out);
}

// round 12
// speedup vs baseline: 1.2079x; 1.0004x over previous
#include <cuda_runtime.h>

// Flow-warp bilinear, direct scalar gather, 2 y-adjacent pixels per thread,
// channels processed in PAIRS with all 16 taps loaded before any compute
// (wider load batching -> more memory-level parallelism per warp).
// Streaming hints on write-once out / read-once flow so src owns L1/L2.
// out[b,c,y,x] = bilerp(src[b,c], clamp(y+flow[b,0,y,x]), clamp(x+flow[b,1,y,x]))
// B=8, C=16, H=W=512.
// Edge trick: clamp x0,y0 <= 510; when floor==511 the fractional weight is
// exactly 1.0 so the result is identical and the +1 taps stay in bounds.

#define B_ 8
#define C_ 16
#define H_ 512
#define W_ 512
#define HW_ (H_ * W_)
#define CHW_ (C_ * HW_)

__global__ void __launch_bounds__(256, 6) warp_gather2p_kernel(
    const float* __restrict__ src,
    const float* __restrict__ flow,
    float* __restrict__ out)
{
    int idx = blockIdx.x * blockDim.x + threadIdx.x;   // over B * H/2 * W
    int x   = idx & (W_ - 1);
    int ry  = (idx >> 9) & 255;
    int b   = idx >> 17;
    int y   = ry * 2;

    const float* __restrict__ fby = flow + b * 2 * HW_;
    const float* __restrict__ fbx = fby + HW_;

    int   g00[2];
    float wxv[2], wyv[2];

#pragma unroll
    for (int k = 0; k < 2; ++k) {
        int yy = y + k;
        int fo = yy * W_ + x;
        float fy = __ldcs(fby + fo);            // read-once: stream
        float fx = __ldcs(fbx + fo);
        // reference's normalize->unnormalize cancels exactly
        float py = fminf(fmaxf((float)yy + fy, 0.0f), (float)(H_ - 1));
        float px = fminf(fmaxf((float)x  + fx, 0.0f), (float)(W_ - 1));
        float y0f = floorf(py);
        float x0f = floorf(px);
        int y0 = min((int)y0f, H_ - 2);         // edge: weight becomes exactly 1
        int x0 = min((int)x0f, W_ - 2);
        wyv[k] = py - (float)y0;
        wxv[k] = px - (float)x0;
        g00[k] = (y0 << 9) + x0;
    }

    const float* __restrict__ sb = src + b * CHW_;
    float* __restrict__ ob = out + b * CHW_ + y * W_ + x;

    const int gA = g00[0];
    const int gB = g00[1];

#pragma unroll
    for (int c = 0; c < C_; c += 2) {
        const float* __restrict__ sc0 = sb + c * HW_;
        const float* __restrict__ sc1 = sc0 + HW_;

        // ---- issue all 16 gathers for two channels up front ----
        float a00 = __ldg(sc0 + gA);
        float a01 = __ldg(sc0 + gA + 1);
        float a10 = __ldg(sc0 + gA + W_);
        float a11 = __ldg(sc0 + gA + W_ + 1);
        float b00 = __ldg(sc0 + gB);
        float b01 = __ldg(sc0 + gB + 1);
        float b10 = __ldg(sc0 + gB + W_);
        float b11 = __ldg(sc0 + gB + W_ + 1);

        float c00 = __ldg(sc1 + gA);
        float c01 = __ldg(sc1 + gA + 1);
        float c10 = __ldg(sc1 + gA + W_);
        float c11 = __ldg(sc1 + gA + W_ + 1);
        float d00 = __ldg(sc1 + gB);
        float d01 = __ldg(sc1 + gB + 1);
        float d10 = __ldg(sc1 + gB + W_);
        float d11 = __ldg(sc1 + gB + W_ + 1);

        // ---- compute + streaming stores ----
        float atop = fmaf(wxv[0], a01 - a00, a00);
        float abot = fmaf(wxv[0], a11 - a10, a10);
        float btop = fmaf(wxv[1], b01 - b00, b00);
        float bbot = fmaf(wxv[1], b11 - b10, b10);

        float ctop = fmaf(wxv[0], c01 - c00, c00);
        float cbot = fmaf(wxv[0], c11 - c10, c10);
        float dtop = fmaf(wxv[1], d01 - d00, d00);
        float dbot = fmaf(wxv[1], d11 - d10, d10);

        float* __restrict__ oc0 = ob + c * HW_;
        float* __restrict__ oc1 = oc0 + HW_;
        __stcs(oc0,      fmaf(wyv[0], abot - atop, atop));
        __stcs(oc0 + W_, fmaf(wyv[1], bbot - btop, btop));
        __stcs(oc1,      fmaf(wyv[0], cbot - ctop, ctop));
        __stcs(oc1 + W_, fmaf(wyv[1], dbot - dtop, dtop));
    }
}

extern "C" void kernel_launch(void* const* d_in, const int* in_sizes, int n_in,
                              void* d_out, int out_size)
{
    const float* src  = (const float*)d_in[0];
    const float* flow = (const float*)d_in[1];
    float* out        = (float*)d_out;

    const int total = B_ * (H_ / 2) * W_;   // 1,048,576 threads
    warp_gather2p_kernel<<<total / 256, 256>>>(src, flow, out);
}